// round 13
// baseline (speedup 1.0000x reference)
#include <cuda_runtime.h>

// GaussianEdgeGuide — prep kernel + smem-free stencil, 2 channels per warp.
//
// Algebra: softmax over the 9 neighborhood positions of
//   -theta*(edge_center + edge_neighbor - max_edge)
// has edge_center and max_edge constant along the softmax axis, so
//   weight_k(q) = E(q+d_k) / S(q),   E(x) = exp(-theta*edge(x)) (E=1 outside),
//   S(q) = sum_k E(q+d_k).
// One iteration: mask'(q) = box3(mask*E)(q) / S(q)   (mask zero-padded).
// iter1 = box3(mask*E) * IE  (IE = W*E),  out = box3(iter1) * W.
//
// Stencil: each warp spans the full 256-px row with 8 px/lane (f4 cols
// 2*lane, 2*lane+1), owns 8 output rows, and processes TWO channels of the
// same batch. E/IE/W rows are loaded once and shared by both channels
// (-37% LDG vs one channel per warp); the two channels give 2x ILP on the
// sum->shuffle->mul chains. 8-px lanes make the quad seam lane-internal:
// horizontal exchange is 1 up + 1 down shuffle per channel, borders are
// pure zero-in at lanes 0/31. No shared memory, no halo loads.
//
// NC=19 odd: pair 9 runs channel 18 in both slots (identical writes to the
// same address -> deterministic; ~5% duplicated work).

#define NB   8
#define NC   19
#define HW   256
#define NPIX (HW * HW)

__device__ __align__(16) float g_E [NB * NPIX];   // exp(-40*edge)
__device__ __align__(16) float g_W [NB * NPIX];   // 1 / box3(E)
__device__ __align__(16) float g_IE[NB * NPIX];   // W * E

__device__ __forceinline__ float4 mul4(float4 a, float4 b)
{
    return make_float4(a.x * b.x, a.y * b.y, a.z * b.z, a.w * b.w);
}

// ---------------------------------------------------------------------------
// Kernel 1: per-pixel E, W, IE (32x32 tiles; unchanged).
// ---------------------------------------------------------------------------
__global__ __launch_bounds__(256, 4)
void geg_prep(const float* __restrict__ edge)
{
    __shared__ float sE[34 * 35];   // 34x34 E with halo 1, E=1 outside image

    const int tid = threadIdx.x;
    const int h0 = blockIdx.y * 32, w0 = blockIdx.x * 32;
    const int n  = blockIdx.z;
    const float* eimg = edge + (n << 16);

    for (int idx = tid; idx < 34 * 34; idx += 256) {
        int i = idx / 34, j = idx - i * 34;
        int gy = h0 - 1 + i, gx = w0 - 1 + j;
        float e = 1.0f;  // exp(-40 * 0) at zero-padded border
        if ((unsigned)gy < 256u && (unsigned)gx < 256u)
            e = __expf(-40.0f * eimg[(gy << 8) + gx]);
        sE[i * 35 + j] = e;
    }
    __syncthreads();

    const int tj = tid & 31, tb = tid >> 5;
    #pragma unroll
    for (int k = 0; k < 4; ++k) {
        int ti = tb + 8 * k;
        const float* p = &sE[ti * 35 + tj];
        float s = p[0]  + p[1]  + p[2]
                + p[35] + p[36] + p[37]
                + p[70] + p[71] + p[72];
        float w  = __fdividef(1.0f, s);
        float ec = p[36];
        int g = (n << 16) + ((h0 + ti) << 8) + (w0 + tj);
        g_E [g] = ec;
        g_W [g] = w;
        g_IE[g] = w * ec;
    }
}

// Load one P = mask*E row (8 px/lane) for both channels; zero outside image.
__device__ __forceinline__ void load_p(float4 d[2][2], int gy, int q0,
                                       const float4* __restrict__ m0,
                                       const float4* __restrict__ m1,
                                       const float4* __restrict__ Eb)
{
    if ((unsigned)gy < 256u) {
        int r = (gy << 6) + q0;
        float4 e0 = Eb[r], e1 = Eb[r + 1];
        d[0][0] = mul4(m0[r],     e0);
        d[0][1] = mul4(m0[r + 1], e1);
        d[1][0] = mul4(m1[r],     e0);
        d[1][1] = mul4(m1[r + 1], e1);
    } else {
        float4 z = make_float4(0.f, 0.f, 0.f, 0.f);
        d[0][0] = z; d[0][1] = z; d[1][0] = z; d[1][1] = z;
    }
}

// ---------------------------------------------------------------------------
// Kernel 2: stencil. Grid (16, NB*10), block 64 (2 warps).
// Warp owns 8 output rows x 256 px x 2 channels.
// ---------------------------------------------------------------------------
__global__ __launch_bounds__(64, 8)
void geg_stencil(const float* __restrict__ mask,
                 float* __restrict__ out)
{
    const unsigned FULL = 0xffffffffu;
    const int lane = threadIdx.x & 31;
    const int warp = threadIdx.x >> 5;     // 0..1
    const int zb = blockIdx.y;             // n * 10 + pair
    const int n  = zb / 10;
    const int pr = zb - n * 10;
    const int c0 = 2 * pr;
    const int c1 = (c0 + 1 < NC) ? c0 + 1 : c0;   // pair 9 duplicates ch 18

    const float4* mc0 = (const float4*)(mask + ((size_t)(n * NC + c0) << 16));
    const float4* mc1 = (const float4*)(mask + ((size_t)(n * NC + c1) << 16));
    float4* oc0 = (float4*)(out + ((size_t)(n * NC + c0) << 16));
    float4* oc1 = (float4*)(out + ((size_t)(n * NC + c1) << 16));
    const float4* Eb  = (const float4*)(g_E  + (n << 16));
    const float4* IEb = (const float4*)(g_IE + (n << 16));
    const float4* Wb  = (const float4*)(g_W  + (n << 16));

    const int q0 = 2 * lane;               // f4 col of px 8*lane
    const int R0 = (blockIdx.x << 4) + (warp << 3);  // first output row

    // rolling state: P rows (mask*E) and iter1 rows, [channel][quad]
    float4 P0[2][2], P1[2][2], P2[2][2];
    float4 M0[2][2], M1[2][2], M2[2][2];

    load_p(P0, R0 - 2, q0, mc0, mc1, Eb);
    load_p(P1, R0 - 1, q0, mc0, mc1, Eb);
    {
        float4 z = make_float4(0.f, 0.f, 0.f, 0.f);
        #pragma unroll
        for (int ch = 0; ch < 2; ++ch) {
            M1[ch][0] = z; M1[ch][1] = z;   // never read before written
            M2[ch][0] = z; M2[ch][1] = z;
        }
    }

    #pragma unroll
    for (int a = R0 - 1; a <= R0 + 8; ++a) {   // iter1 row a
        load_p(P2, a + 1, q0, mc0, mc1, Eb);
        const bool arow = (unsigned)a < 256u;
        float4 ie0, ie1;
        if (arow) { int ri = (a << 6) + q0; ie0 = IEb[ri]; ie1 = IEb[ri + 1]; }

        #pragma unroll
        for (int ch = 0; ch < 2; ++ch) {
            // vertical 3-sums over 8 columns
            float s1 = P0[ch][0].x + P1[ch][0].x + P2[ch][0].x;
            float s2 = P0[ch][0].y + P1[ch][0].y + P2[ch][0].y;
            float s3 = P0[ch][0].z + P1[ch][0].z + P2[ch][0].z;
            float s4 = P0[ch][0].w + P1[ch][0].w + P2[ch][0].w;
            float s5 = P0[ch][1].x + P1[ch][1].x + P2[ch][1].x;
            float s6 = P0[ch][1].y + P1[ch][1].y + P2[ch][1].y;
            float s7 = P0[ch][1].z + P1[ch][1].z + P2[ch][1].z;
            float s8 = P0[ch][1].w + P1[ch][1].w + P2[ch][1].w;

            float l = __shfl_up_sync  (FULL, s8, 1);
            float r = __shfl_down_sync(FULL, s1, 1);
            if (lane == 0)  l = 0.f;   // px -1  -> zero-pad
            if (lane == 31) r = 0.f;   // px 256 -> zero-pad

            float4 mr0, mr1;
            if (arow) {
                mr0 = make_float4((l  + s1 + s2) * ie0.x,
                                  (s1 + s2 + s3) * ie0.y,
                                  (s2 + s3 + s4) * ie0.z,
                                  (s3 + s4 + s5) * ie0.w);
                mr1 = make_float4((s4 + s5 + s6) * ie1.x,
                                  (s5 + s6 + s7) * ie1.y,
                                  (s6 + s7 + s8) * ie1.z,
                                  (s7 + s8 + r ) * ie1.w);
            } else {
                mr0 = make_float4(0.f, 0.f, 0.f, 0.f);
                mr1 = mr0;
            }

            // roll M and P
            M0[ch][0] = M1[ch][0]; M0[ch][1] = M1[ch][1];
            M1[ch][0] = M2[ch][0]; M1[ch][1] = M2[ch][1];
            M2[ch][0] = mr0;       M2[ch][1] = mr1;
            P0[ch][0] = P1[ch][0]; P0[ch][1] = P1[ch][1];
            P1[ch][0] = P2[ch][0]; P1[ch][1] = P2[ch][1];
        }

        if (a >= R0 + 1) {                 // output row r = a-1, in [0,255]
            int rr = a - 1;
            int ri = (rr << 6) + q0;
            float4 w0 = Wb[ri], w1 = Wb[ri + 1];

            #pragma unroll
            for (int ch = 0; ch < 2; ++ch) {
                float v1 = M0[ch][0].x + M1[ch][0].x + M2[ch][0].x;
                float v2 = M0[ch][0].y + M1[ch][0].y + M2[ch][0].y;
                float v3 = M0[ch][0].z + M1[ch][0].z + M2[ch][0].z;
                float v4 = M0[ch][0].w + M1[ch][0].w + M2[ch][0].w;
                float v5 = M0[ch][1].x + M1[ch][1].x + M2[ch][1].x;
                float v6 = M0[ch][1].y + M1[ch][1].y + M2[ch][1].y;
                float v7 = M0[ch][1].z + M1[ch][1].z + M2[ch][1].z;
                float v8 = M0[ch][1].w + M1[ch][1].w + M2[ch][1].w;

                float l = __shfl_up_sync  (FULL, v8, 1);
                float r = __shfl_down_sync(FULL, v1, 1);
                if (lane == 0)  l = 0.f;
                if (lane == 31) r = 0.f;

                float4 o0 = make_float4((l  + v1 + v2) * w0.x,
                                        (v1 + v2 + v3) * w0.y,
                                        (v2 + v3 + v4) * w0.z,
                                        (v3 + v4 + v5) * w0.w);
                float4 o1 = make_float4((v4 + v5 + v6) * w1.x,
                                        (v5 + v6 + v7) * w1.y,
                                        (v6 + v7 + v8) * w1.z,
                                        (v7 + v8 + r ) * w1.w);
                if (ch == 0) { oc0[ri] = o0; oc0[ri + 1] = o1; }
                else         { oc1[ri] = o0; oc1[ri + 1] = o1; }
            }
        }
    }
}

extern "C" void kernel_launch(void* const* d_in, const int* in_sizes, int n_in,
                              void* d_out, int out_size)
{
    const float* mask = (const float*)d_in[0];
    const float* edge = (const float*)d_in[1];
    // d_in[2] = iter_n is fixed at 2 by the problem setup; 2 iterations fused.
    (void)in_sizes; (void)n_in; (void)out_size;

    dim3 gp(HW / 32, HW / 32, NB);            // 8 x 8 x 8
    geg_prep<<<gp, 256>>>(edge);

    dim3 gs(HW / 16, NB * 10);                // 16 x 80 = 1280 CTAs
    geg_stencil<<<gs, 64>>>(mask, (float*)d_out);
}